// round 1
// baseline (speedup 1.0000x reference)
#include <cuda_runtime.h>
#include <cstdint>

#define HW (128*128)
#define BATCH 8

// ---------------- scratch (no allocations allowed) ----------------
__device__ float g_om[BATCH*27*HW];      // conv output: offsets raw, mask = 2*sigmoid
__device__ float g_wt_dc[9*64*64];       // [kf][c][o]
__device__ float g_wt_om[9*64*32];       // [kf][c][o], o padded 27->32 with zeros

// ---------------- f32x2 helpers ----------------
__device__ __forceinline__ unsigned long long pack2(float lo, float hi){
    unsigned long long r;
    asm("mov.b64 %0, {%1, %2};" : "=l"(r) : "f"(lo), "f"(hi));
    return r;
}
__device__ __forceinline__ void unpack2(unsigned long long v, float &lo, float &hi){
    asm("mov.b64 {%0, %1}, %2;" : "=f"(lo), "=f"(hi) : "l"(v));
}
__device__ __forceinline__ void ffma2(unsigned long long &d, unsigned long long a, unsigned long long b){
    asm("fma.rn.f32x2 %0, %1, %2, %0;" : "+l"(d) : "l"(a), "l"(b));
}

// ---------------- kernel 0: weight transpose/pad ----------------
__global__ void prep_kernel(const float* __restrict__ w_om, const float* __restrict__ w_dc){
    int i = blockIdx.x * blockDim.x + threadIdx.x;
    if (i < 9*64*64) {
        int o = i & 63, c = (i >> 6) & 63, kf = i >> 12;
        g_wt_dc[i] = w_dc[(o*64 + c)*9 + kf];
    }
    int j = i - 9*64*64;
    if (j >= 0 && j < 9*64*32) {
        int o = j & 31, c = (j >> 5) & 63, kf = j >> 11;
        g_wt_om[j] = (o < 27) ? w_om[(o*64 + c)*9 + kf] : 0.f;
    }
}

// ---------------- kernel 1: 3x3 conv 64->27 (+2*sigmoid on mask channels) ----------------
// grid (64 row-tiles, 8 batch), 128 threads. Tile = 2 rows x 128 cols = 256 px.
// thread: og = warp id (4 groups of 8 out-ch, padded to 32), pm = lane (8 px).
__global__ void __launch_bounds__(128, 2)
conv_om_kernel(const float* __restrict__ x, const float* __restrict__ b_om){
    extern __shared__ char smem[];
    float*  Xs  = (float*)smem;                      // [64][256]
    float2* Wss = (float2*)(smem + 64*256*4);        // [64][32] splatted

    const int b  = blockIdx.y;
    const int r0 = blockIdx.x * 2;
    const int t  = threadIdx.x;
    const int og = t >> 5;     // 0..3
    const int pm = t & 31;
    const float* xb = x + (size_t)b * 64 * HW;

    unsigned long long acc[8][4];
    #pragma unroll
    for (int oi = 0; oi < 8; ++oi){
        int o = og*8 + oi;
        float bv = (o < 27) ? b_om[o] : 0.f;
        unsigned long long pb = pack2(bv, bv);
        #pragma unroll
        for (int k = 0; k < 4; ++k) acc[oi][k] = pb;
    }

    for (int kf = 0; kf < 9; ++kf){
        __syncthreads();   // protect Xs/Wss from previous GEMM readers
        // stage splatted weights for this tap
        for (int i = t; i < 64*32; i += 128){
            float w = g_wt_om[(kf << 11) + i];
            Wss[i] = make_float2(w, w);
        }
        const int ky = kf/3 - 1, kx = kf%3 - 1;
        // gather shifted x (zero pad), 2 px per thread
        #pragma unroll
        for (int s = 0; s < 2; ++s){
            int pp = t + s*128;
            int row = r0 + (pp >> 7);
            int col = pp & 127;
            int yy = row + ky, xx = col + kx;
            bool v = (yy >= 0 && yy < 128 && xx >= 0 && xx < 128);
            int idx = yy*128 + xx;
            #pragma unroll 8
            for (int c = 0; c < 64; ++c)
                Xs[c*256 + pp] = v ? xb[c*HW + idx] : 0.f;
        }
        __syncthreads();
        // GEMM accumulate: K-chunk = 64 channels
        #pragma unroll 8
        for (int c = 0; c < 64; ++c){
            const ulonglong2* vrow = (const ulonglong2*)(Xs + c*256);
            ulonglong2 va = vrow[pm];
            ulonglong2 vb = vrow[32 + pm];
            const ulonglong2* wrow = (const ulonglong2*)(Wss + c*32);
            #pragma unroll
            for (int j = 0; j < 4; ++j){
                ulonglong2 wp = wrow[og*4 + j];
                ffma2(acc[2*j  ][0], va.x, wp.x);
                ffma2(acc[2*j  ][1], va.y, wp.x);
                ffma2(acc[2*j  ][2], vb.x, wp.x);
                ffma2(acc[2*j  ][3], vb.y, wp.x);
                ffma2(acc[2*j+1][0], va.x, wp.y);
                ffma2(acc[2*j+1][1], va.y, wp.y);
                ffma2(acc[2*j+1][2], vb.x, wp.y);
                ffma2(acc[2*j+1][3], vb.y, wp.y);
            }
        }
    }

    // epilogue: channels <18 raw offsets, 18..26 -> 2*sigmoid (mask)
    #pragma unroll
    for (int oi = 0; oi < 8; ++oi){
        int o = og*8 + oi;
        if (o >= 27) continue;             // og uniform per warp -> no divergence
        float v0,v1,v2,v3,v4,v5,v6,v7;
        unpack2(acc[oi][0], v0, v1);
        unpack2(acc[oi][1], v2, v3);
        unpack2(acc[oi][2], v4, v5);
        unpack2(acc[oi][3], v6, v7);
        if (o >= 18){
            v0 = 2.f/(1.f + __expf(-v0)); v1 = 2.f/(1.f + __expf(-v1));
            v2 = 2.f/(1.f + __expf(-v2)); v3 = 2.f/(1.f + __expf(-v3));
            v4 = 2.f/(1.f + __expf(-v4)); v5 = 2.f/(1.f + __expf(-v5));
            v6 = 2.f/(1.f + __expf(-v6)); v7 = 2.f/(1.f + __expf(-v7));
        }
        float* dst = g_om + (size_t)(b*27 + o)*HW + r0*128 + pm*4;
        *(float4*)dst         = make_float4(v0, v1, v2, v3);
        *(float4*)(dst + 128) = make_float4(v4, v5, v6, v7);
    }
}

// ---------------- kernel 2: deformable conv 64->64 ----------------
// grid (64 row-tiles, 8 batch), 256 threads. Tile = 2 rows x 128 = 256 px.
// per tap: gather masked bilinear into Vs[64][256], then f32x2 GEMM.
__global__ void __launch_bounds__(256, 2)
deform_kernel(const float* __restrict__ x, const float* __restrict__ b_dc,
              float* __restrict__ out){
    extern __shared__ char smem[];
    float*  Vs  = (float*)smem;                      // [64][256]
    float2* Wss = (float2*)(smem + 64*256*4);        // [64][64] splatted

    const int b  = blockIdx.y;
    const int r0 = blockIdx.x * 2;
    const int t  = threadIdx.x;
    const int om = t >> 5;     // warp id 0..7 -> 8 out channels each
    const int pm = t & 31;     // 8 px each
    const int row = r0 + (t >> 7);
    const int col = t & 127;
    const int pix = row*128 + col;
    const float* xb  = x + (size_t)b * 64 * HW;
    const float* omb = g_om + (size_t)b * 27 * HW;

    unsigned long long acc[8][4];
    #pragma unroll
    for (int oi = 0; oi < 8; ++oi){
        float bv = b_dc[om*8 + oi];
        unsigned long long pb = pack2(bv, bv);
        #pragma unroll
        for (int k = 0; k < 4; ++k) acc[oi][k] = pb;
    }

    for (int kf = 0; kf < 9; ++kf){
        __syncthreads();   // protect Vs/Wss from previous GEMM readers
        // stage splatted weights for this tap
        for (int i = t; i < 64*64; i += 256){
            float w = g_wt_dc[(kf << 12) + i];
            Wss[i] = make_float2(w, w);
        }
        // bilinear corner setup for this thread's pixel
        float offy = omb[(2*kf    )*HW + pix];
        float offx = omb[(2*kf + 1)*HW + pix];
        float m    = omb[(18 + kf )*HW + pix];
        float py = (float)(row - 1 + kf/3) + offy;
        float px = (float)(col - 1 + kf%3) + offx;
        float y0f = floorf(py), x0f = floorf(px);
        float fy = py - y0f, fx = px - x0f;
        int y0 = (int)y0f, x0 = (int)x0f;
        int y1 = y0 + 1,   x1 = x0 + 1;
        float vy0 = (y0 >= 0 && y0 <= 127) ? 1.f : 0.f;
        float vy1 = (y1 >= 0 && y1 <= 127) ? 1.f : 0.f;
        float vx0 = (x0 >= 0 && x0 <= 127) ? 1.f : 0.f;
        float vx1 = (x1 >= 0 && x1 <= 127) ? 1.f : 0.f;
        float w00 = (1.f-fy)*(1.f-fx) * vy0*vx0 * m;
        float w01 = (1.f-fy)*fx       * vy0*vx1 * m;
        float w10 = fy*(1.f-fx)       * vy1*vx0 * m;
        float w11 = fy*fx             * vy1*vx1 * m;
        int cy0 = min(max(y0,0),127), cy1 = min(max(y1,0),127);
        int cx0 = min(max(x0,0),127), cx1 = min(max(x1,0),127);
        int i00 = cy0*128 + cx0, i01 = cy0*128 + cx1;
        int i10 = cy1*128 + cx0, i11 = cy1*128 + cx1;

        // gather all 64 channels for this pixel
        #pragma unroll 4
        for (int c = 0; c < 64; ++c){
            const float* bc = xb + c*HW;
            float v = w00*bc[i00] + w01*bc[i01] + w10*bc[i10] + w11*bc[i11];
            Vs[c*256 + t] = v;
        }
        __syncthreads();
        // GEMM accumulate: K-chunk = 64 channels
        #pragma unroll 8
        for (int c = 0; c < 64; ++c){
            const ulonglong2* vrow = (const ulonglong2*)(Vs + c*256);
            ulonglong2 va = vrow[pm];
            ulonglong2 vb = vrow[32 + pm];
            const ulonglong2* wrow = (const ulonglong2*)(Wss + c*64);
            #pragma unroll
            for (int j = 0; j < 4; ++j){
                ulonglong2 wp = wrow[om*4 + j];
                ffma2(acc[2*j  ][0], va.x, wp.x);
                ffma2(acc[2*j  ][1], va.y, wp.x);
                ffma2(acc[2*j  ][2], vb.x, wp.x);
                ffma2(acc[2*j  ][3], vb.y, wp.x);
                ffma2(acc[2*j+1][0], va.x, wp.y);
                ffma2(acc[2*j+1][1], va.y, wp.y);
                ffma2(acc[2*j+1][2], vb.x, wp.y);
                ffma2(acc[2*j+1][3], vb.y, wp.y);
            }
        }
    }

    // epilogue
    #pragma unroll
    for (int oi = 0; oi < 8; ++oi){
        int o = om*8 + oi;
        float v0,v1,v2,v3,v4,v5,v6,v7;
        unpack2(acc[oi][0], v0, v1);
        unpack2(acc[oi][1], v2, v3);
        unpack2(acc[oi][2], v4, v5);
        unpack2(acc[oi][3], v6, v7);
        float* dst = out + (size_t)(b*64 + o)*HW + r0*128 + pm*4;
        *(float4*)dst         = make_float4(v0, v1, v2, v3);
        *(float4*)(dst + 128) = make_float4(v4, v5, v6, v7);
    }
}

// ---------------- launch ----------------
extern "C" void kernel_launch(void* const* d_in, const int* in_sizes, int n_in,
                              void* d_out, int out_size){
    const float* x    = (const float*)d_in[0];
    const float* w_om = (const float*)d_in[1];
    const float* b_om = (const float*)d_in[2];
    const float* w_dc = (const float*)d_in[3];
    const float* b_dc = (const float*)d_in[4];
    float* out = (float*)d_out;

    cudaFuncSetAttribute(conv_om_kernel, cudaFuncAttributeMaxDynamicSharedMemorySize, 64*256*4 + 64*32*8);
    cudaFuncSetAttribute(deform_kernel,  cudaFuncAttributeMaxDynamicSharedMemorySize, 64*256*4 + 64*64*8);

    prep_kernel<<<216, 256>>>(w_om, w_dc);
    conv_om_kernel<<<dim3(64, 8), 128, 64*256*4 + 64*32*8>>>(x, b_om);
    deform_kernel <<<dim3(64, 8), 256, 64*256*4 + 64*64*8>>>(x, b_dc, out);
}

// round 2
// speedup vs baseline: 1.0499x; 1.0499x over previous
#include <cuda_runtime.h>
#include <cstdint>

#define HW (128*128)
#define BATCH 8

// ---------------- scratch (no allocations allowed) ----------------
__device__ float g_om[BATCH*27*HW];      // conv output: offsets raw, mask = 2*sigmoid
__device__ float g_wt_dc[9*64*64];       // [kf][c][o]
__device__ float g_wt_om[9*64*32];       // [kf][c][o], o padded 27->32 with zeros

// ---------------- f32x2 helpers ----------------
__device__ __forceinline__ unsigned long long pack2(float lo, float hi){
    unsigned long long r;
    asm("mov.b64 %0, {%1, %2};" : "=l"(r) : "f"(lo), "f"(hi));
    return r;
}
__device__ __forceinline__ void unpack2(unsigned long long v, float &lo, float &hi){
    asm("mov.b64 {%0, %1}, %2;" : "=f"(lo), "=f"(hi) : "l"(v));
}
__device__ __forceinline__ void ffma2(unsigned long long &d, unsigned long long a, unsigned long long b){
    asm("fma.rn.f32x2 %0, %1, %2, %0;" : "+l"(d) : "l"(a), "l"(b));
}

// ---------------- kernel 0: weight transpose/pad ----------------
__global__ void prep_kernel(const float* __restrict__ w_om, const float* __restrict__ w_dc){
    int i = blockIdx.x * blockDim.x + threadIdx.x;
    if (i < 9*64*64) {
        int o = i & 63, c = (i >> 6) & 63, kf = i >> 12;
        g_wt_dc[i] = w_dc[(o*64 + c)*9 + kf];
    }
    int j = i - 9*64*64;
    if (j >= 0 && j < 9*64*32) {
        int o = j & 31, c = (j >> 5) & 63, kf = j >> 11;
        g_wt_om[j] = (o < 27) ? w_om[(o*64 + c)*9 + kf] : 0.f;
    }
}

// =====================================================================
// kernel 1: 3x3 conv 64->27(+sigmoid mask), pipelined double-buffered
// grid (64 row-tiles, 8 batch), 256 threads. Tile = 2 rows x 128 = 256 px.
// warp w handles out-ch [4w, 4w+4); lane pm handles px {4pm..4pm+3, 128+4pm..}
// =====================================================================
#define CONV_SMEM (2*64*256*4 + 2*64*32*8)
__global__ void __launch_bounds__(256, 1)
conv_om_kernel(const float* __restrict__ x, const float* __restrict__ b_om){
    extern __shared__ char smem[];
    float*  Xs = (float*)smem;                         // [2][64][256]
    float2* Ws = (float2*)(smem + 2*64*256*4);         // [2][64][32]

    const int b  = blockIdx.y;
    const int r0 = blockIdx.x * 2;
    const int t  = threadIdx.x;
    const int wid = t >> 5;
    const int pm  = t & 31;
    const int row = r0 + (t >> 7);
    const int col = t & 127;
    const float* xb = x + (size_t)b * 64 * HW;

    unsigned long long acc[4][4];
    #pragma unroll
    for (int oi = 0; oi < 4; ++oi){
        int o = wid*4 + oi;
        float bv = (o < 27) ? b_om[o] : 0.f;
        unsigned long long pb = pack2(bv, bv);
        #pragma unroll
        for (int k = 0; k < 4; ++k) acc[oi][k] = pb;
    }

    // ---- prologue: stage tap 0 ----
    {
        int yy = row - 1, xx = col - 1;
        bool v = (yy >= 0 && xx >= 0);           // tap 0: ky=kx=-1, upper bounds safe
        int idx = yy*128 + xx;
        #pragma unroll 8
        for (int c = 0; c < 64; ++c)
            Xs[c*256 + t] = v ? xb[c*HW + idx] : 0.f;
        #pragma unroll
        for (int i = t; i < 64*32; i += 256){
            float w = g_wt_om[i];
            Ws[i] = make_float2(w, w);
        }
    }
    __syncthreads();

    for (int kf = 0; kf < 9; ++kf){
        const int cur = kf & 1;
        float*  XsC = Xs + cur*(64*256);
        float2* WsC = Ws + cur*(64*32);
        float*  XsN = Xs + (cur^1)*(64*256);
        float2* WsN = Ws + (cur^1)*(64*32);
        const bool hn = (kf < 8);

        int idxN = 0; bool vN = false;
        if (hn){
            const int kn = kf + 1;
            const int ky = kn/3 - 1, kx = kn%3 - 1;
            int yy = row + ky, xx = col + kx;
            vN = (yy >= 0 && yy < 128 && xx >= 0 && xx < 128);
            idxN = yy*128 + xx;
            #pragma unroll
            for (int i = t; i < 64*32; i += 256){
                float w = g_wt_om[(kn << 11) + i];
                WsN[i] = make_float2(w, w);
            }
        }

        #pragma unroll
        for (int seg = 0; seg < 4; ++seg){
            const int c0 = seg * 16;
            if (hn){
                #pragma unroll
                for (int c = c0; c < c0 + 16; ++c)
                    XsN[c*256 + t] = vN ? xb[c*HW + idxN] : 0.f;
            }
            #pragma unroll
            for (int c = c0; c < c0 + 16; ++c){
                const ulonglong2* vrow = (const ulonglong2*)(XsC + c*256);
                ulonglong2 va = vrow[pm];
                ulonglong2 vb = vrow[32 + pm];
                const ulonglong2* wrow = (const ulonglong2*)(WsC + c*32);
                ulonglong2 w0 = wrow[wid*2];
                ulonglong2 w1 = wrow[wid*2 + 1];
                ffma2(acc[0][0], va.x, w0.x); ffma2(acc[0][1], va.y, w0.x);
                ffma2(acc[0][2], vb.x, w0.x); ffma2(acc[0][3], vb.y, w0.x);
                ffma2(acc[1][0], va.x, w0.y); ffma2(acc[1][1], va.y, w0.y);
                ffma2(acc[1][2], vb.x, w0.y); ffma2(acc[1][3], vb.y, w0.y);
                ffma2(acc[2][0], va.x, w1.x); ffma2(acc[2][1], va.y, w1.x);
                ffma2(acc[2][2], vb.x, w1.x); ffma2(acc[2][3], vb.y, w1.x);
                ffma2(acc[3][0], va.x, w1.y); ffma2(acc[3][1], va.y, w1.y);
                ffma2(acc[3][2], vb.x, w1.y); ffma2(acc[3][3], vb.y, w1.y);
            }
        }
        __syncthreads();
    }

    // epilogue: channels <18 raw offsets, 18..26 -> 2*sigmoid (mask)
    #pragma unroll
    for (int oi = 0; oi < 4; ++oi){
        int o = wid*4 + oi;
        if (o >= 27) continue;
        float v0,v1,v2,v3,v4,v5,v6,v7;
        unpack2(acc[oi][0], v0, v1);
        unpack2(acc[oi][1], v2, v3);
        unpack2(acc[oi][2], v4, v5);
        unpack2(acc[oi][3], v6, v7);
        if (o >= 18){
            v0 = 2.f/(1.f + __expf(-v0)); v1 = 2.f/(1.f + __expf(-v1));
            v2 = 2.f/(1.f + __expf(-v2)); v3 = 2.f/(1.f + __expf(-v3));
            v4 = 2.f/(1.f + __expf(-v4)); v5 = 2.f/(1.f + __expf(-v5));
            v6 = 2.f/(1.f + __expf(-v6)); v7 = 2.f/(1.f + __expf(-v7));
        }
        float* dst = g_om + (size_t)(b*27 + o)*HW + r0*128 + pm*4;
        *(float4*)dst         = make_float4(v0, v1, v2, v3);
        *(float4*)(dst + 128) = make_float4(v4, v5, v6, v7);
    }
}

// =====================================================================
// kernel 2: deformable conv 64->64, pipelined double-buffered
// grid (64 row-tiles, 8 batch), 256 threads. Tile = 2 rows x 128 = 256 px.
// warp w handles out-ch [8w, 8w+8)
// =====================================================================
#define DEF_SMEM (2*64*256*4 + 2*64*64*8)

struct BilinSetup { float w00, w01, w10, w11; int i00, i01, i10, i11; };

__device__ __forceinline__ BilinSetup bilin_setup(const float* omb, int kf, int row, int col, int pix){
    BilinSetup s;
    float offy = omb[(2*kf    )*HW + pix];
    float offx = omb[(2*kf + 1)*HW + pix];
    float m    = omb[(18 + kf )*HW + pix];
    float py = (float)(row - 1 + kf/3) + offy;
    float px = (float)(col - 1 + kf%3) + offx;
    float y0f = floorf(py), x0f = floorf(px);
    float fy = py - y0f, fx = px - x0f;
    int y0 = (int)y0f, x0 = (int)x0f;
    int y1 = y0 + 1,   x1 = x0 + 1;
    float vy0 = (y0 >= 0 && y0 <= 127) ? 1.f : 0.f;
    float vy1 = (y1 >= 0 && y1 <= 127) ? 1.f : 0.f;
    float vx0 = (x0 >= 0 && x0 <= 127) ? 1.f : 0.f;
    float vx1 = (x1 >= 0 && x1 <= 127) ? 1.f : 0.f;
    s.w00 = (1.f-fy)*(1.f-fx) * vy0*vx0 * m;
    s.w01 = (1.f-fy)*fx       * vy0*vx1 * m;
    s.w10 = fy*(1.f-fx)       * vy1*vx0 * m;
    s.w11 = fy*fx             * vy1*vx1 * m;
    int cy0 = min(max(y0,0),127), cy1 = min(max(y1,0),127);
    int cx0 = min(max(x0,0),127), cx1 = min(max(x1,0),127);
    s.i00 = cy0*128 + cx0; s.i01 = cy0*128 + cx1;
    s.i10 = cy1*128 + cx0; s.i11 = cy1*128 + cx1;
    return s;
}

__global__ void __launch_bounds__(256, 1)
deform_kernel(const float* __restrict__ x, const float* __restrict__ b_dc,
              float* __restrict__ out){
    extern __shared__ char smem[];
    float*  Vs = (float*)smem;                        // [2][64][256]
    float2* Ws = (float2*)(smem + 2*64*256*4);        // [2][64][64]

    const int b  = blockIdx.y;
    const int r0 = blockIdx.x * 2;
    const int t  = threadIdx.x;
    const int om = t >> 5;
    const int pm = t & 31;
    const int row = r0 + (t >> 7);
    const int col = t & 127;
    const int pix = row*128 + col;
    const float* xb  = x + (size_t)b * 64 * HW;
    const float* omb = g_om + (size_t)b * 27 * HW;

    unsigned long long acc[8][4];
    #pragma unroll
    for (int oi = 0; oi < 8; ++oi){
        float bv = b_dc[om*8 + oi];
        unsigned long long pb = pack2(bv, bv);
        #pragma unroll
        for (int k = 0; k < 4; ++k) acc[oi][k] = pb;
    }

    // ---- prologue: gather tap 0 + stage its weights ----
    {
        BilinSetup s = bilin_setup(omb, 0, row, col, pix);
        #pragma unroll 8
        for (int c = 0; c < 64; ++c){
            const float* bc = xb + c*HW;
            Vs[c*256 + t] = s.w00*bc[s.i00] + s.w01*bc[s.i01]
                          + s.w10*bc[s.i10] + s.w11*bc[s.i11];
        }
        #pragma unroll
        for (int i = t; i < 64*64; i += 256){
            float w = g_wt_dc[i];
            Ws[i] = make_float2(w, w);
        }
    }
    __syncthreads();

    for (int kf = 0; kf < 9; ++kf){
        const int cur = kf & 1;
        float*  VsC = Vs + cur*(64*256);
        float2* WsC = Ws + cur*(64*64);
        float*  VsN = Vs + (cur^1)*(64*256);
        float2* WsN = Ws + (cur^1)*(64*64);
        const bool hn = (kf < 8);

        BilinSetup s;
        if (hn){
            const int kn = kf + 1;
            s = bilin_setup(omb, kn, row, col, pix);
            #pragma unroll
            for (int i = t; i < 64*64; i += 256){
                float w = g_wt_dc[(kn << 12) + i];
                WsN[i] = make_float2(w, w);
            }
        }

        #pragma unroll
        for (int seg = 0; seg < 4; ++seg){
            const int c0 = seg * 16;
            if (hn){
                #pragma unroll
                for (int c = c0; c < c0 + 16; ++c){
                    const float* bc = xb + c*HW;
                    VsN[c*256 + t] = s.w00*bc[s.i00] + s.w01*bc[s.i01]
                                   + s.w10*bc[s.i10] + s.w11*bc[s.i11];
                }
            }
            #pragma unroll
            for (int c = c0; c < c0 + 16; ++c){
                const ulonglong2* vrow = (const ulonglong2*)(VsC + c*256);
                ulonglong2 va = vrow[pm];
                ulonglong2 vb = vrow[32 + pm];
                const ulonglong2* wrow = (const ulonglong2*)(WsC + c*64);
                #pragma unroll
                for (int j = 0; j < 4; ++j){
                    ulonglong2 wp = wrow[om*4 + j];
                    ffma2(acc[2*j  ][0], va.x, wp.x);
                    ffma2(acc[2*j  ][1], va.y, wp.x);
                    ffma2(acc[2*j  ][2], vb.x, wp.x);
                    ffma2(acc[2*j  ][3], vb.y, wp.x);
                    ffma2(acc[2*j+1][0], va.x, wp.y);
                    ffma2(acc[2*j+1][1], va.y, wp.y);
                    ffma2(acc[2*j+1][2], vb.x, wp.y);
                    ffma2(acc[2*j+1][3], vb.y, wp.y);
                }
            }
        }
        __syncthreads();
    }

    // epilogue
    #pragma unroll
    for (int oi = 0; oi < 8; ++oi){
        int o = om*8 + oi;
        float v0,v1,v2,v3,v4,v5,v6,v7;
        unpack2(acc[oi][0], v0, v1);
        unpack2(acc[oi][1], v2, v3);
        unpack2(acc[oi][2], v4, v5);
        unpack2(acc[oi][3], v6, v7);
        float* dst = out + (size_t)(b*64 + o)*HW + r0*128 + pm*4;
        *(float4*)dst         = make_float4(v0, v1, v2, v3);
        *(float4*)(dst + 128) = make_float4(v4, v5, v6, v7);
    }
}

// ---------------- launch ----------------
extern "C" void kernel_launch(void* const* d_in, const int* in_sizes, int n_in,
                              void* d_out, int out_size){
    const float* x    = (const float*)d_in[0];
    const float* w_om = (const float*)d_in[1];
    const float* b_om = (const float*)d_in[2];
    const float* w_dc = (const float*)d_in[3];
    const float* b_dc = (const float*)d_in[4];
    float* out = (float*)d_out;

    cudaFuncSetAttribute(conv_om_kernel, cudaFuncAttributeMaxDynamicSharedMemorySize, CONV_SMEM);
    cudaFuncSetAttribute(deform_kernel,  cudaFuncAttributeMaxDynamicSharedMemorySize, DEF_SMEM);

    prep_kernel<<<216, 256>>>(w_om, w_dc);
    conv_om_kernel<<<dim3(64, 8), 256, CONV_SMEM>>>(x, b_om);
    deform_kernel <<<dim3(64, 8), 256, DEF_SMEM>>>(x, b_dc, out);
}

// round 4
// speedup vs baseline: 1.8588x; 1.7705x over previous
#include <cuda_runtime.h>
#include <cuda_fp16.h>
#include <cstdint>

#define HW (128*128)

// ---------------- scratch (no allocations allowed) ----------------
__device__ float  g_om[8*27*HW];          // conv1 out: offsets raw, mask = 2*sigmoid
__device__ __half g_wdc_h[9*2*4096];      // [kf][hi/lo][oc(64)][c(64)]
__device__ __half g_wom_h[9*2*2048];      // [kf][hi/lo][oc(32, 27 used)][c(64)]

// ---------------- helpers ----------------
__device__ __forceinline__ uint32_t smem_u32(const void* p){
    uint32_t a;
    asm("{ .reg .u64 t; cvta.to.shared.u64 t, %1; cvt.u32.u64 %0, t; }" : "=r"(a) : "l"(p));
    return a;
}
__device__ __forceinline__ void ldsm_x4(uint32_t &r0,uint32_t &r1,uint32_t &r2,uint32_t &r3, uint32_t addr){
    asm volatile("ldmatrix.sync.aligned.m8n8.x4.shared.b16 {%0,%1,%2,%3}, [%4];"
        : "=r"(r0),"=r"(r1),"=r"(r2),"=r"(r3) : "r"(addr));
}
__device__ __forceinline__ void ldsm_x2(uint32_t &r0,uint32_t &r1, uint32_t addr){
    asm volatile("ldmatrix.sync.aligned.m8n8.x2.shared.b16 {%0,%1}, [%2];"
        : "=r"(r0),"=r"(r1) : "r"(addr));
}
__device__ __forceinline__ void mma16816(float* d, const uint32_t* a, const uint32_t* b){
    asm volatile("mma.sync.aligned.m16n8k16.row.col.f32.f16.f16.f32 "
        "{%0,%1,%2,%3}, {%4,%5,%6,%7}, {%8,%9}, {%0,%1,%2,%3};"
        : "+f"(d[0]),"+f"(d[1]),"+f"(d[2]),"+f"(d[3])
        : "r"(a[0]),"r"(a[1]),"r"(a[2]),"r"(a[3]), "r"(b[0]),"r"(b[1]));
}
// pack 2 floats -> f16x2 hi, return residuals
__device__ __forceinline__ uint32_t pack_hi(float a, float b, float &ra, float &rb){
    __half ha = __float2half_rn(a), hb = __float2half_rn(b);
    ra = a - __half2float(ha); rb = b - __half2float(hb);
    __half2 h2 = __halves2half2(ha, hb);
    return *(uint32_t*)&h2;
}
__device__ __forceinline__ uint32_t pack_lo(float ra, float rb){
    __half2 l2 = __floats2half2_rn(ra, rb);
    return *(uint32_t*)&l2;
}

__constant__ int cKY[9] = {-1,-1,-1, 0,0,0, 1,1,1};
__constant__ int cKX[9] = {-1, 0, 1,-1,0,1,-1,0,1};

// ---------------- kernel 0: weight split fp32 -> f16 hi/lo ----------------
__global__ void prep_kernel(const float* __restrict__ w_om, const float* __restrict__ w_dc){
    int i = blockIdx.x * blockDim.x + threadIdx.x;
    if (i < 9*4096){                     // deform: kf, oc(64), c(64)
        int kf = i >> 12, rem = i & 4095;
        int oc = rem >> 6, c = rem & 63;
        float w = w_dc[(oc*64 + c)*9 + kf];
        __half hi = __float2half_rn(w);
        __half lo = __float2half_rn(w - __half2float(hi));
        g_wdc_h[kf*8192 + rem]        = hi;
        g_wdc_h[kf*8192 + 4096 + rem] = lo;
    }
    int j = i - 9*4096;
    if (j >= 0 && j < 9*2048){           // conv1: kf, oc(32), c(64)
        int kf = j >> 11, rem = j & 2047;
        int oc = rem >> 6, c = rem & 63;
        float w = (oc < 27) ? w_om[(oc*64 + c)*9 + kf] : 0.f;
        __half hi = __float2half_rn(w);
        __half lo = __float2half_rn(w - __half2float(hi));
        g_wom_h[kf*4096 + rem]        = hi;
        g_wom_h[kf*4096 + 2048 + rem] = lo;
    }
}

// =====================================================================
// smem tile geometry: rows padded to 72 halves (144 B) for conflict-free
// ldmatrix (stride = 9 x 16B -> 8 consecutive rows hit distinct 16B cols)
// =====================================================================
#define RSTRIDE 144

// conv stage: Xhi[128px][72h] 18432 | Xlo 18432 | Whi[32][72h] 4608 | Wlo 4608
#define CV_XHI  0
#define CV_XLO  18432
#define CV_WHI  36864
#define CV_WLO  41472
#define CV_STG  46080
#define CV_SMEM (2*CV_STG)

// deform stage: Vhi 18432 | Vlo 18432 | Whi[64][72h] 9216 | Wlo 9216
#define DF_VHI  0
#define DF_VLO  18432
#define DF_WHI  36864
#define DF_WLO  46080
#define DF_STG  55296
#define DF_SMEM (2*DF_STG)

// shared GEMM core: A = values[128px][64c] hi/lo, B = W[n][64c] hi/lo,
// D[16px x 8n] fp32 frags per warp. NC = n-chunks (8 for deform, 4 for conv).
template<int NC>
__device__ __forceinline__ void mma_tap(uint32_t stg, int vhi_off, int vlo_off,
                                        int whi_off, int wlo_off,
                                        int lane, int px0, float d[NC][4]){
    const int arow = px0 + (lane & 15);
    const int akof = (lane >> 4) * 16;               // bytes: (lane>>4)*8 halves
    const uint32_t aBaseHi = stg + vhi_off + arow*RSTRIDE + akof;
    const uint32_t aBaseLo = stg + vlo_off + arow*RSTRIDE + akof;
    const int brow = (lane & 7);
    const int bkof = ((lane >> 3) & 1) * 16;
    uint32_t ah[4][4], al[4][4];
    #pragma unroll
    for (int kc = 0; kc < 4; ++kc){
        ldsm_x4(ah[kc][0],ah[kc][1],ah[kc][2],ah[kc][3], aBaseHi + kc*32);
        ldsm_x4(al[kc][0],al[kc][1],al[kc][2],al[kc][3], aBaseLo + kc*32);
    }
    #pragma unroll
    for (int nc = 0; nc < NC; ++nc){
        uint32_t bh[4][2], bl[4][2];
        const uint32_t bRow = (nc*8 + brow)*RSTRIDE + bkof;
        #pragma unroll
        for (int kc = 0; kc < 4; ++kc){
            ldsm_x2(bh[kc][0], bh[kc][1], stg + whi_off + bRow + kc*32);
            ldsm_x2(bl[kc][0], bl[kc][1], stg + wlo_off + bRow + kc*32);
        }
        #pragma unroll
        for (int kc = 0; kc < 4; ++kc){
            mma16816(d[nc], ah[kc], bh[kc]);
            mma16816(d[nc], ah[kc], bl[kc]);
            mma16816(d[nc], al[kc], bh[kc]);
        }
    }
}

// =====================================================================
// kernel 1: 3x3 conv 64->27 (+2*sigmoid) via f16x3 mma.sync
// CTA = one image row, grid (128, 8), 256 threads (8 warps x 16 px).
// =====================================================================
__global__ void __launch_bounds__(256, 1)
conv_om_kernel(const float* __restrict__ x, const float* __restrict__ b_om){
    extern __shared__ char smem[];
    const uint32_t sb = smem_u32(smem);
    const int b   = blockIdx.y;
    const int row = blockIdx.x;
    const int t   = threadIdx.x;
    const int w   = t >> 5, lane = t & 31;
    const int px  = t & 127;
    const int ch0 = (t >> 7) * 32;
    const float* xb = x + (size_t)b * 64 * HW;

    float d[4][4];
    #pragma unroll
    for (int i = 0; i < 4; ++i)
        #pragma unroll
        for (int k = 0; k < 4; ++k) d[i][k] = 0.f;

    // gather for tap kf into buffer buf
    auto gather = [&](int kf, int buf){
        char* sg = smem + buf*CV_STG;
        // weights: 2048 halves hi + 2048 lo, 256 x 8-half chunks each
        {
            const __half* src = g_wom_h + kf*4096;
            int oc = t >> 3, seg = t & 7;
            ((uint4*)(sg + CV_WHI + oc*RSTRIDE + seg*16))[0] = ((const uint4*)src)[t];
            ((uint4*)(sg + CV_WLO + oc*RSTRIDE + seg*16))[0] = ((const uint4*)(src + 2048))[t];
        }
        int yy = row + cKY[kf], xx = px + cKX[kf];
        bool ok = (yy >= 0 && yy < 128 && xx >= 0 && xx < 128);
        int idx = yy*128 + xx;
        #pragma unroll
        for (int g = 0; g < 4; ++g){
            float v[8];
            #pragma unroll
            for (int j = 0; j < 8; ++j)
                v[j] = ok ? xb[(size_t)(ch0 + 8*g + j)*HW + idx] : 0.f;
            uint32_t hi[4], lo[4];
            #pragma unroll
            for (int j = 0; j < 4; ++j){
                float r0, r1;
                hi[j] = pack_hi(v[2*j], v[2*j+1], r0, r1);
                lo[j] = pack_lo(r0, r1);
            }
            *(uint4*)(sg + CV_XHI + px*RSTRIDE + (ch0 + 8*g)*2) = make_uint4(hi[0],hi[1],hi[2],hi[3]);
            *(uint4*)(sg + CV_XLO + px*RSTRIDE + (ch0 + 8*g)*2) = make_uint4(lo[0],lo[1],lo[2],lo[3]);
        }
    };

    gather(0, 0);
    for (int s = 0; s < 9; ++s){
        __syncthreads();
        if (s < 8) gather(s + 1, (s + 1) & 1);
        mma_tap<4>(sb + (s & 1)*CV_STG, CV_XHI, CV_XLO, CV_WHI, CV_WLO,
                   lane, w*16, d);
    }

    // epilogue: bias + 2*sigmoid on oc>=18, write oc<27 to g_om
    const int g  = lane >> 2, t4 = lane & 3;
    float* dstb = g_om + (size_t)b*27*HW + row*128;
    #pragma unroll
    for (int nc = 0; nc < 4; ++nc){
        int oc0 = 8*nc + 2*t4;
        #pragma unroll
        for (int q = 0; q < 2; ++q){
            int oc = oc0 + q;
            if (oc >= 27) continue;
            float bv = b_om[oc];
            float v0 = d[nc][q]     + bv;   // px = 16w+g
            float v1 = d[nc][q + 2] + bv;   // px = 16w+g+8
            if (oc >= 18){
                v0 = 2.f/(1.f + __expf(-v0));
                v1 = 2.f/(1.f + __expf(-v1));
            }
            dstb[(size_t)oc*HW + w*16 + g]     = v0;
            dstb[(size_t)oc*HW + w*16 + g + 8] = v1;
        }
    }
}

// =====================================================================
// kernel 2: deformable conv 64->64 via f16x3 mma.sync
// CTA = one image row, grid (128, 8), 256 threads.
// =====================================================================
__global__ void __launch_bounds__(256, 1)
deform_kernel(const float* __restrict__ x, const float* __restrict__ b_dc,
              float* __restrict__ out){
    extern __shared__ char smem[];
    const uint32_t sb = smem_u32(smem);
    const int b   = blockIdx.y;
    const int row = blockIdx.x;
    const int t   = threadIdx.x;
    const int w   = t >> 5, lane = t & 31;
    const int px  = t & 127;
    const int ch0 = (t >> 7) * 32;
    const int pix = row*128 + px;
    const float* xb  = x + (size_t)b * 64 * HW;
    const float* omb = g_om + (size_t)b * 27 * HW;

    float d[8][4];
    #pragma unroll
    for (int i = 0; i < 8; ++i)
        #pragma unroll
        for (int k = 0; k < 4; ++k) d[i][k] = 0.f;

    auto gather = [&](int kf, int buf){
        char* sg = smem + buf*DF_STG;
        // weights: 4096 halves hi + 4096 lo = 512 x 8-half chunks each
        {
            const __half* src = g_wdc_h + kf*8192;
            #pragma unroll
            for (int p = 0; p < 2; ++p){
                int j = t + p*256;
                int oc = j >> 3, seg = j & 7;
                ((uint4*)(sg + DF_WHI + oc*RSTRIDE + seg*16))[0] = ((const uint4*)src)[j];
                ((uint4*)(sg + DF_WLO + oc*RSTRIDE + seg*16))[0] = ((const uint4*)(src + 4096))[j];
            }
        }
        // bilinear setup at this pixel
        float offy = omb[(size_t)(2*kf    )*HW + pix];
        float offx = omb[(size_t)(2*kf + 1)*HW + pix];
        float m    = omb[(size_t)(18 + kf )*HW + pix];
        float py = (float)(row + cKY[kf]) + offy;
        float pxf= (float)(px  + cKX[kf]) + offx;
        float y0f = floorf(py), x0f = floorf(pxf);
        float fy = py - y0f, fx = pxf - x0f;
        int y0 = (int)y0f, x0 = (int)x0f, y1 = y0 + 1, x1 = x0 + 1;
        float vy0 = (y0 >= 0 && y0 <= 127) ? 1.f : 0.f;
        float vy1 = (y1 >= 0 && y1 <= 127) ? 1.f : 0.f;
        float vx0 = (x0 >= 0 && x0 <= 127) ? 1.f : 0.f;
        float vx1 = (x1 >= 0 && x1 <= 127) ? 1.f : 0.f;
        float w00 = (1.f-fy)*(1.f-fx)*vy0*vx0*m;
        float w01 = (1.f-fy)*fx      *vy0*vx1*m;
        float w10 = fy*(1.f-fx)      *vy1*vx0*m;
        float w11 = fy*fx            *vy1*vx1*m;
        int cy0 = min(max(y0,0),127), cy1 = min(max(y1,0),127);
        int cx0 = min(max(x0,0),127), cx1 = min(max(x1,0),127);
        int i00 = cy0*128 + cx0, i01 = cy0*128 + cx1;
        int i10 = cy1*128 + cx0, i11 = cy1*128 + cx1;

        #pragma unroll
        for (int g = 0; g < 4; ++g){
            float v[8];
            #pragma unroll
            for (int j = 0; j < 8; ++j){
                const float* bc = xb + (size_t)(ch0 + 8*g + j)*HW;
                v[j] = w00*bc[i00] + w01*bc[i01] + w10*bc[i10] + w11*bc[i11];
            }
            uint32_t hi[4], lo[4];
            #pragma unroll
            for (int j = 0; j < 4; ++j){
                float r0, r1;
                hi[j] = pack_hi(v[2*j], v[2*j+1], r0, r1);
                lo[j] = pack_lo(r0, r1);
            }
            *(uint4*)(sg + DF_VHI + px*RSTRIDE + (ch0 + 8*g)*2) = make_uint4(hi[0],hi[1],hi[2],hi[3]);
            *(uint4*)(sg + DF_VLO + px*RSTRIDE + (ch0 + 8*g)*2) = make_uint4(lo[0],lo[1],lo[2],lo[3]);
        }
    };

    gather(0, 0);
    for (int s = 0; s < 9; ++s){
        __syncthreads();
        if (s < 8) gather(s + 1, (s + 1) & 1);
        mma_tap<8>(sb + (s & 1)*DF_STG, DF_VHI, DF_VLO, DF_WHI, DF_WLO,
                   lane, w*16, d);
    }

    // epilogue: bias, write to out
    const int g  = lane >> 2, t4 = lane & 3;
    float* dstb = out + (size_t)b*64*HW + row*128;
    #pragma unroll
    for (int nc = 0; nc < 8; ++nc){
        int oc0 = 8*nc + 2*t4;
        #pragma unroll
        for (int q = 0; q < 2; ++q){
            int oc = oc0 + q;
            float bv = b_dc[oc];
            dstb[(size_t)oc*HW + w*16 + g]     = d[nc][q]     + bv;
            dstb[(size_t)oc*HW + w*16 + g + 8] = d[nc][q + 2] + bv;
        }
    }
}

// ---------------- launch ----------------
extern "C" void kernel_launch(void* const* d_in, const int* in_sizes, int n_in,
                              void* d_out, int out_size){
    const float* x    = (const float*)d_in[0];
    const float* w_om = (const float*)d_in[1];
    const float* b_om = (const float*)d_in[2];
    const float* w_dc = (const float*)d_in[3];
    const float* b_dc = (const float*)d_in[4];
    float* out = (float*)d_out;

    cudaFuncSetAttribute(conv_om_kernel, cudaFuncAttributeMaxDynamicSharedMemorySize, CV_SMEM);
    cudaFuncSetAttribute(deform_kernel,  cudaFuncAttributeMaxDynamicSharedMemorySize, DF_SMEM);

    prep_kernel<<<216, 256>>>(w_om, w_dc);   // 216*256 = 55296 = 9*4096 + 9*2048
    conv_om_kernel<<<dim3(128, 8), 256, CV_SMEM>>>(x, b_om);
    deform_kernel <<<dim3(128, 8), 256, DF_SMEM>>>(x, b_dc, out);
}